// round 6
// baseline (speedup 1.0000x reference)
#include <cuda_runtime.h>
#include <cuda_bf16.h>
#include <cstdint>

#define N_NODES 100000
#define N_EDGES 600000
#define DIM     128
#define N_REL   8
#define NKEY    (N_NODES * N_REL)               // 800000
#define TILE    128
#define N_TILES ((N_NODES + TILE - 1) / TILE)   // 782
#define GSTR    132                              // smem row stride (floats), pad for banks
#define SMEM_BYTES (2 * TILE * GSTR * 4)         // G tile + W tile, 135168 B

#define SCAN_NB 196                              // ceil(800000 / 4096)

// ---------------- device scratch (no allocations allowed) ----------------
__device__ int g_cnt[NKEY];
__device__ int g_off[NKEY + 1];
__device__ int g_cur[NKEY];
__device__ int g_srcs[N_EDGES];
__device__ int g_bsum[SCAN_NB];
__device__ int g_boff[SCAN_NB];
__device__ __align__(16) float g_wt[N_REL * DIM * DIM];  // [r][h][k], tf32-rounded, transposed
__device__ __align__(16) float g_rt[DIM * DIM];          // [h][k],    tf32-rounded, transposed

// ---------------- helpers ----------------
__device__ __forceinline__ float f2tf(float f) {
    uint32_t u;
    asm("cvt.rna.tf32.f32 %0, %1;" : "=r"(u) : "f"(f));
    return __uint_as_float(u);
}

__device__ __forceinline__ void mma_tf32(float* c, const uint32_t* a, uint32_t b0, uint32_t b1) {
    asm("mma.sync.aligned.m16n8k8.row.col.f32.tf32.tf32.f32 "
        "{%0,%1,%2,%3}, {%4,%5,%6,%7}, {%8,%9}, {%0,%1,%2,%3};"
        : "+f"(c[0]), "+f"(c[1]), "+f"(c[2]), "+f"(c[3])
        : "r"(a[0]), "r"(a[1]), "r"(a[2]), "r"(a[3]), "r"(b0), "r"(b1));
}

// ---------------- preprocessing: counting sort of edges by (dst, rel) ----------------
__global__ void k_zero() {
    int i = blockIdx.x * blockDim.x + threadIdx.x;
    if (i < NKEY) g_cnt[i] = 0;
}

__global__ void k_hist(const int* __restrict__ ei, const int* __restrict__ et) {
    int e = blockIdx.x * blockDim.x + threadIdx.x;
    if (e < N_EDGES) {
        int dst = ei[N_EDGES + e];
        int r   = et[e];
        atomicAdd(&g_cnt[dst * N_REL + r], 1);
    }
}

__global__ void k_scan_block() {
    __shared__ int s[1024];
    int tid = threadIdx.x, bid = blockIdx.x;
    int base = bid * 4096 + tid * 4;
    int v[4]; int tsum = 0;
#pragma unroll
    for (int j = 0; j < 4; j++) {
        v[j] = (base + j < NKEY) ? g_cnt[base + j] : 0;
        tsum += v[j];
    }
    s[tid] = tsum; __syncthreads();
    for (int d = 1; d < 1024; d <<= 1) {
        int t = (tid >= d) ? s[tid - d] : 0;
        __syncthreads();
        s[tid] += t;
        __syncthreads();
    }
    int excl = s[tid] - tsum;
    if (tid == 0) g_bsum[bid] = s[1023];
    int run = excl;
#pragma unroll
    for (int j = 0; j < 4; j++) {
        if (base + j < NKEY) g_off[base + j] = run;
        run += v[j];
    }
}

__global__ void k_scan_sums() {
    __shared__ int s[256];
    int tid = threadIdx.x;
    int v = (tid < SCAN_NB) ? g_bsum[tid] : 0;
    s[tid] = v; __syncthreads();
    for (int d = 1; d < 256; d <<= 1) {
        int t = (tid >= d) ? s[tid - d] : 0;
        __syncthreads();
        s[tid] += t;
        __syncthreads();
    }
    if (tid < SCAN_NB) g_boff[tid] = s[tid] - v;
    if (tid == 0) g_off[NKEY] = N_EDGES;
}

__global__ void k_scan_add() {
    int tid = threadIdx.x, bid = blockIdx.x;
    int add = g_boff[bid];
    int base = bid * 4096 + tid * 4;
#pragma unroll
    for (int j = 0; j < 4; j++) {
        int idx = base + j;
        if (idx < NKEY) {
            int t = g_off[idx] + add;
            g_off[idx] = t;
            g_cur[idx] = t;
        }
    }
}

__global__ void k_scatter(const int* __restrict__ ei, const int* __restrict__ et) {
    int e = blockIdx.x * blockDim.x + threadIdx.x;
    if (e < N_EDGES) {
        int src = ei[e];
        int dst = ei[N_EDGES + e];
        int key = dst * N_REL + et[e];
        int p = atomicAdd(&g_cur[key], 1);
        g_srcs[p] = src;
    }
}

// W: [r][k][h]  ->  g_wt: [r][h][k]  (transposed, tf32-rounded).  root likewise.
__global__ void k_prep(const float* __restrict__ W, const float* __restrict__ root) {
    int i = blockIdx.x * blockDim.x + threadIdx.x;
    int nw = N_REL * DIM * DIM;
    if (i < nw) {
        int r = i / (DIM * DIM);
        int k = (i / DIM) % DIM;
        int h = i % DIM;
        g_wt[r * DIM * DIM + h * DIM + k] = f2tf(W[i]);
    } else if (i < nw + DIM * DIM) {
        int j = i - nw;
        int k = j / DIM, h = j % DIM;
        g_rt[h * DIM + k] = f2tf(root[j]);
    }
}

// ---------------- fused gather + 9x GEMM-accumulate + epilogue ----------------
__global__ void __launch_bounds__(512, 1)
k_main(const float* __restrict__ x, const float* __restrict__ bias, float* __restrict__ out) {
    extern __shared__ float sm[];
    float* Gs = sm;                   // [128][GSTR]  A operand (dst-tile features, tf32)
    float* Ws = sm + TILE * GSTR;     // [128][GSTR]  B operand ([h][k], tf32)

    const int tid  = threadIdx.x;
    const int lane = tid & 31;
    const int w    = tid >> 5;        // 16 warps
    const int g    = lane >> 2;       // group id 0..7
    const int tg   = lane & 3;        // thread-in-group 0..3
    const int tile = blockIdx.x;

    const int moff = (w & 3) * 32;
    const int noff = (w >> 2) * 32;

    const float4* x4 = (const float4*)x;

    float acc[2][4][4];
#pragma unroll
    for (int a = 0; a < 2; a++)
#pragma unroll
        for (int b = 0; b < 4; b++)
#pragma unroll
            for (int c = 0; c < 4; c++) acc[a][b][c] = 0.f;

    for (int it = 0; it < N_REL + 1; ++it) {
        // ---- stage B operand: W_r (or root), already [h][k] tf32 in global ----
        const float4* w4 = (it < N_REL) ? (const float4*)(g_wt + it * DIM * DIM)
                                        : (const float4*)g_rt;
        for (int i = tid; i < DIM * DIM / 4; i += 512) {   // 4096 float4
            int h = i >> 5, k4 = i & 31;
            ((float4*)(Ws + h * GSTR))[k4] = w4[i];
        }

        // ---- stage A operand: per-relation mean-aggregated features (or raw x) ----
#pragma unroll
        for (int ii = 0; ii < 8; ++ii) {
            int id = tid + ii * 512;          // 0..4095
            int d  = id >> 5;                 // local dst row (warp-uniform)
            int cg = id & 31;                 // float4 column group
            int dg = tile * TILE + d;
            float4 s4 = make_float4(0.f, 0.f, 0.f, 0.f);
            float scale = 1.f;
            if (it < N_REL) {
                if (dg < N_NODES) {
                    int key = dg * N_REL + it;
                    int s0 = g_off[key], s1 = g_off[key + 1];
                    for (int e = s0; e < s1; ++e) {
                        float4 xv = x4[g_srcs[e] * 32 + cg];
                        s4.x += xv.x; s4.y += xv.y; s4.z += xv.z; s4.w += xv.w;
                    }
                    int len = s1 - s0;
                    scale = 1.f / (float)max(len, 1);
                }
            } else {
                if (dg < N_NODES) s4 = x4[dg * 32 + cg];
            }
            float4 t4;
            t4.x = f2tf(s4.x * scale);
            t4.y = f2tf(s4.y * scale);
            t4.z = f2tf(s4.z * scale);
            t4.w = f2tf(s4.w * scale);
            ((float4*)(Gs + d * GSTR))[cg] = t4;
        }
        __syncthreads();

        // ---- MMA accumulate: warp computes its 32x32 subtile ----
#pragma unroll
        for (int kt = 0; kt < 16; ++kt) {
            const int k0 = kt * 8;
            uint32_t a[2][4];
#pragma unroll
            for (int mi = 0; mi < 2; mi++) {
                const float* gp = Gs + (moff + mi * 16 + g) * GSTR + k0;
                a[mi][0] = __float_as_uint(gp[tg]);
                a[mi][1] = __float_as_uint(gp[8 * GSTR + tg]);
                a[mi][2] = __float_as_uint(gp[tg + 4]);
                a[mi][3] = __float_as_uint(gp[8 * GSTR + tg + 4]);
            }
#pragma unroll
            for (int ni = 0; ni < 4; ni++) {
                const float* wp = Ws + (noff + ni * 8 + g) * GSTR + k0;
                uint32_t b0 = __float_as_uint(wp[tg]);
                uint32_t b1 = __float_as_uint(wp[tg + 4]);
                mma_tf32(acc[0][ni], a[0], b0, b1);
                mma_tf32(acc[1][ni], a[1], b0, b1);
            }
        }
        __syncthreads();
    }

    // ---- epilogue: bias + relu + store ----
#pragma unroll
    for (int ni = 0; ni < 4; ni++) {
        int col = noff + ni * 8 + tg * 2;
        float b0 = bias[col], b1 = bias[col + 1];
#pragma unroll
        for (int mi = 0; mi < 2; mi++) {
            int row0 = tile * TILE + moff + mi * 16 + g;
            int row1 = row0 + 8;
            if (row0 < N_NODES) {
                float2 o;
                o.x = fmaxf(acc[mi][ni][0] + b0, 0.f);
                o.y = fmaxf(acc[mi][ni][1] + b1, 0.f);
                ((float2*)out)[row0 * 64 + (col >> 1)] = o;
            }
            if (row1 < N_NODES) {
                float2 o;
                o.x = fmaxf(acc[mi][ni][2] + b0, 0.f);
                o.y = fmaxf(acc[mi][ni][3] + b1, 0.f);
                ((float2*)out)[row1 * 64 + (col >> 1)] = o;
            }
        }
    }
}

// ---------------- launcher ----------------
extern "C" void kernel_launch(void* const* d_in, const int* in_sizes, int n_in,
                              void* d_out, int out_size) {
    const float* x    = (const float*)d_in[0];
    const int*   ei   = (const int*)d_in[1];
    const int*   et   = (const int*)d_in[2];
    const float* W    = (const float*)d_in[3];
    const float* root = (const float*)d_in[4];
    const float* bias = (const float*)d_in[5];
    float* out = (float*)d_out;

    cudaFuncSetAttribute(k_main, cudaFuncAttributeMaxDynamicSharedMemorySize, SMEM_BYTES);

    k_zero<<<(NKEY + 1023) / 1024, 1024>>>();
    k_hist<<<(N_EDGES + 255) / 256, 256>>>(ei, et);
    k_scan_block<<<SCAN_NB, 1024>>>();
    k_scan_sums<<<1, 256>>>();
    k_scan_add<<<SCAN_NB, 1024>>>();
    k_scatter<<<(N_EDGES + 255) / 256, 256>>>(ei, et);
    k_prep<<<(N_REL * DIM * DIM + DIM * DIM + 255) / 256, 256>>>(W, root);
    k_main<<<N_TILES, 512, SMEM_BYTES>>>(x, bias, out);
}

// round 16
// speedup vs baseline: 1.1693x; 1.1693x over previous
#include <cuda_runtime.h>
#include <cuda_bf16.h>
#include <cstdint>

#define N_NODES 100000
#define N_EDGES 600000
#define DIM     128
#define N_REL   8
#define NKEY    (N_NODES * N_REL)               // 800000
#define TILE    128
#define N_TILES ((N_NODES + TILE - 1) / TILE)   // 782
#define SCAN_NB 196                              // ceil(800000 / 4096)
#define GSTR    132                              // smem row stride (floats)

// ---- k_main smem layout (bytes) ----
#define SMEM_GOFF  0                              // 1025 ints
#define SKEDGE     2048
#define SMEM_SRCS  4112                           // SKEDGE ints
#define SMEM_A0    12320                          // 128xGSTR floats (67584 B)
#define SMEM_A1    (SMEM_A0 + TILE * GSTR * 4)    // 79904
#define SMEM_W     (SMEM_A1 + TILE * GSTR * 4)    // 147488
#define SMEM_TOTAL (SMEM_W + TILE * GSTR * 4)     // 215072 B

// ---------------- device scratch ----------------
__device__ int g_cnt[NKEY];
__device__ int g_off[NKEY + 1];
__device__ int g_cur[NKEY];
__device__ int g_srcs[N_EDGES];
__device__ int g_bsum[SCAN_NB];
__device__ int g_boff[SCAN_NB];
__device__ __align__(16) float g_wt[N_REL * DIM * DIM];  // [r][h][k] tf32-rounded (W^T)
__device__ __align__(16) float g_rt[DIM * DIM];          // [h][k]    tf32-rounded (root^T)

// ---------------- helpers ----------------
__device__ __forceinline__ float f2tf(float f) {
    uint32_t u;
    asm("cvt.rna.tf32.f32 %0, %1;" : "=r"(u) : "f"(f));
    return __uint_as_float(u);
}

__device__ __forceinline__ uint32_t smem_u32(const void* p) {
    uint32_t a;
    asm("{ .reg .u64 t; cvta.to.shared.u64 t, %1; cvt.u32.u64 %0, t; }" : "=r"(a) : "l"(p));
    return a;
}

__device__ __forceinline__ void cp16(void* dst_smem, const void* src) {
    asm volatile("cp.async.cg.shared.global [%0], [%1], 16;"
                 :: "r"(smem_u32(dst_smem)), "l"(src) : "memory");
}
__device__ __forceinline__ void cp_wait_all() {
    asm volatile("cp.async.commit_group;\ncp.async.wait_group 0;" ::: "memory");
}

__device__ __forceinline__ void mma_tf32(float* c, const uint32_t* a, uint32_t b0, uint32_t b1) {
    asm("mma.sync.aligned.m16n8k8.row.col.f32.tf32.tf32.f32 "
        "{%0,%1,%2,%3}, {%4,%5,%6,%7}, {%8,%9}, {%0,%1,%2,%3};"
        : "+f"(c[0]), "+f"(c[1]), "+f"(c[2]), "+f"(c[3])
        : "r"(a[0]), "r"(a[1]), "r"(a[2]), "r"(a[3]), "r"(b0), "r"(b1));
}

// ---------------- preprocessing ----------------
// fused: zero the histogram AND tf32-transpose the weights (independent work)
__global__ void k_zero_prep(const float* __restrict__ W, const float* __restrict__ root) {
    int bid = blockIdx.x, tid = threadIdx.x;
    if (bid < 782) {
        int i = bid * 1024 + tid;
        if (i < NKEY) g_cnt[i] = 0;
    } else {
        int i = (bid - 782) * 1024 + tid;
        int nw = N_REL * DIM * DIM;
        if (i < nw) {
            int r = i / (DIM * DIM);
            int k = (i / DIM) % DIM;
            int h = i % DIM;
            g_wt[r * DIM * DIM + h * DIM + k] = f2tf(W[i]);
        } else if (i < nw + DIM * DIM) {
            int j = i - nw;
            int k = j / DIM, h = j % DIM;
            g_rt[h * DIM + k] = f2tf(root[j]);
        }
    }
}

__global__ void k_hist(const int* __restrict__ ei, const int* __restrict__ et) {
    int e = blockIdx.x * blockDim.x + threadIdx.x;
    if (e < N_EDGES) {
        int dst = ei[N_EDGES + e];
        atomicAdd(&g_cnt[dst * N_REL + et[e]], 1);
    }
}

__global__ void k_scan_block() {
    __shared__ int s[1024];
    int tid = threadIdx.x, bid = blockIdx.x;
    int base = bid * 4096 + tid * 4;
    int v[4]; int tsum = 0;
#pragma unroll
    for (int j = 0; j < 4; j++) {
        v[j] = (base + j < NKEY) ? g_cnt[base + j] : 0;
        tsum += v[j];
    }
    s[tid] = tsum; __syncthreads();
    for (int d = 1; d < 1024; d <<= 1) {
        int t = (tid >= d) ? s[tid - d] : 0;
        __syncthreads();
        s[tid] += t;
        __syncthreads();
    }
    int excl = s[tid] - tsum;
    if (tid == 0) g_bsum[bid] = s[1023];
    int run = excl;
#pragma unroll
    for (int j = 0; j < 4; j++) {
        if (base + j < NKEY) g_off[base + j] = run;
        run += v[j];
    }
}

__global__ void k_scan_sums() {
    __shared__ int s[256];
    int tid = threadIdx.x;
    int v = (tid < SCAN_NB) ? g_bsum[tid] : 0;
    s[tid] = v; __syncthreads();
    for (int d = 1; d < 256; d <<= 1) {
        int t = (tid >= d) ? s[tid - d] : 0;
        __syncthreads();
        s[tid] += t;
        __syncthreads();
    }
    if (tid < SCAN_NB) g_boff[tid] = s[tid] - v;
    if (tid == 0) g_off[NKEY] = N_EDGES;
}

__global__ void k_scan_add() {
    int tid = threadIdx.x, bid = blockIdx.x;
    int add = g_boff[bid];
    int base = bid * 4096 + tid * 4;
#pragma unroll
    for (int j = 0; j < 4; j++) {
        int idx = base + j;
        if (idx < NKEY) {
            int t = g_off[idx] + add;
            g_off[idx] = t;
            g_cur[idx] = t;
        }
    }
}

__global__ void k_scatter(const int* __restrict__ ei, const int* __restrict__ et) {
    int e = blockIdx.x * blockDim.x + threadIdx.x;
    if (e < N_EDGES) {
        int src = ei[e];
        int dst = ei[N_EDGES + e];
        int key = dst * N_REL + et[e];
        int p = atomicAdd(&g_cur[key], 1);
        g_srcs[p] = src;
    }
}

// ---------------- fused gather + pipelined mma.sync GEMM + epilogue ----------------
// 512 threads = 16 warps. K-split: warps 0-7 do K[0:64), warps 8-15 do K[64:128).
// Within each K-half: 2 (m) x 4 (n) warps, each owning a 64x32 output subtile.
__global__ void __launch_bounds__(512, 1)
k_main(const float* __restrict__ x, const float* __restrict__ bias, float* __restrict__ out) {
    extern __shared__ char sm[];
    const int tid  = threadIdx.x;
    const int lane = tid & 31;
    const int w    = tid >> 5;
    const int g    = lane >> 2;       // 0..7
    const int tg   = lane & 3;        // 0..3
    const int tile = blockIdx.x;

    const int wk    = w >> 3;          // K-half
    const int wmn   = w & 7;
    const int moff  = (wmn & 1) * 64;
    const int noff  = (wmn >> 1) * 32;
    const int kwoff = wk * 8;          // kt offset (units of 8 k)

    int*   s_goff = (int*)(sm + SMEM_GOFF);
    int*   s_srcs = (int*)(sm + SMEM_SRCS);
    float* A0     = (float*)(sm + SMEM_A0);
    float* A1     = (float*)(sm + SMEM_A1);
    float* Wb     = (float*)(sm + SMEM_W);

    // ---- stage tile CSR offsets ----
    for (int j = tid; j < 1025; j += 512) {
        int k = tile * 1024 + j;
        s_goff[j] = (k <= NKEY) ? g_off[k] : N_EDGES;
    }
    __syncthreads();

    const int e0   = s_goff[0];
    const int ecnt = s_goff[1024] - e0;
    const bool esm = (ecnt <= SKEDGE);
    if (esm) {
        for (int e = tid; e < ecnt; e += 512) s_srcs[e] = g_srcs[e0 + e];
    }
    __syncthreads();   // <-- R11 FIX: s_srcs must be visible to all threads before stage_A

    const float4* x4 = (const float4*)x;

    float acc[4][4][4];
#pragma unroll
    for (int a = 0; a < 4; a++)
#pragma unroll
        for (int b = 0; b < 4; b++)
#pragma unroll
            for (int c = 0; c < 4; c++) acc[a][b][c] = 0.f;

    // ---- A staging: gather + mean + tf32 round into Abuf ----
    auto stage_A = [&](int it, float* Abuf) {
#pragma unroll
        for (int ii = 0; ii < 8; ++ii) {
            int id = tid + ii * 512;          // 0..4095
            int d  = id >> 5;
            int cg = id & 31;
            int dg = tile * TILE + d;
            float4 s4 = make_float4(0.f, 0.f, 0.f, 0.f);
            float scale = 1.f;
            if (it < N_REL) {
                if (dg < N_NODES) {
                    int s0 = s_goff[d * 8 + it], s1 = s_goff[d * 8 + it + 1];
                    if (esm) {
                        for (int e = s0; e < s1; ++e) {
                            float4 xv = x4[s_srcs[e - e0] * 32 + cg];
                            s4.x += xv.x; s4.y += xv.y; s4.z += xv.z; s4.w += xv.w;
                        }
                    } else {
                        for (int e = s0; e < s1; ++e) {
                            float4 xv = x4[g_srcs[e] * 32 + cg];
                            s4.x += xv.x; s4.y += xv.y; s4.z += xv.z; s4.w += xv.w;
                        }
                    }
                    scale = 1.f / (float)max(s1 - s0, 1);
                }
            } else {
                if (dg < N_NODES) s4 = x4[dg * 32 + cg];
            }
            float4 t4;
            t4.x = f2tf(s4.x * scale);
            t4.y = f2tf(s4.y * scale);
            t4.z = f2tf(s4.z * scale);
            t4.w = f2tf(s4.w * scale);
            *(float4*)(Abuf + d * GSTR + cg * 4) = t4;
        }
    };

    auto stage_W = [&](int it) {
        const float4* w4 = (it < N_REL) ? (const float4*)(g_wt + it * DIM * DIM)
                                        : (const float4*)g_rt;
#pragma unroll
        for (int ii = 0; ii < 8; ++ii) {
            int i = tid + ii * 512;
            int h = i >> 5, cg = i & 31;
            cp16(Wb + h * GSTR + cg * 4, w4 + i);
        }
        cp_wait_all();
    };

    // ---- prologue: stage relation 0 ----
    stage_W(0);
    stage_A(0, A0);
    __syncthreads();

    // ---- pipelined main loop: mma(s) overlaps stage_A(s+1) ----
    for (int s = 0; s <= N_REL; ++s) {
        const float* Acur = (s & 1) ? A1 : A0;
        float*       Anxt = (s & 1) ? A0 : A1;

        if (s < N_REL) stage_A(s + 1, Anxt);   // LDG/gather, fills other buffer

#pragma unroll
        for (int kt = 0; kt < 8; ++kt) {
            const int k0 = (kwoff + kt) * 8;
            uint32_t a[4][4];
#pragma unroll
            for (int mi = 0; mi < 4; mi++) {
                const float* gp = Acur + (moff + mi * 16 + g) * GSTR + k0;
                a[mi][0] = __float_as_uint(gp[tg]);
                a[mi][1] = __float_as_uint(gp[8 * GSTR + tg]);
                a[mi][2] = __float_as_uint(gp[tg + 4]);
                a[mi][3] = __float_as_uint(gp[8 * GSTR + tg + 4]);
            }
#pragma unroll
            for (int ni = 0; ni < 4; ni++) {
                const float* wp = Wb + (noff + ni * 8 + g) * GSTR + k0;
                uint32_t b0 = __float_as_uint(wp[tg]);
                uint32_t b1 = __float_as_uint(wp[tg + 4]);
#pragma unroll
                for (int mi = 0; mi < 4; mi++) mma_tf32(acc[mi][ni], a[mi], b0, b1);
            }
        }
        __syncthreads();
        if (s < N_REL) {           // W single-buffered: refill after all mma(s) done
            stage_W(s + 1);
            __syncthreads();
        }
    }

    // ---- K-split reduction: wk=1 partials -> smem (reuse W buffer) ----
    float* red = Wb;                       // 256 slots x 66 floats = 16896 floats
    const int slot = (wmn * 32 + lane) * 66;
    if (wk == 1) {
#pragma unroll
        for (int mi = 0; mi < 4; mi++)
#pragma unroll
            for (int ni = 0; ni < 4; ni++) {
                int t = (mi * 4 + ni) * 4;
                *(float2*)(red + slot + t)     = make_float2(acc[mi][ni][0], acc[mi][ni][1]);
                *(float2*)(red + slot + t + 2) = make_float2(acc[mi][ni][2], acc[mi][ni][3]);
            }
    }
    __syncthreads();

    // ---- epilogue (wk=0 warps): add partner partials, bias + relu, store ----
    if (wk == 0) {
#pragma unroll
        for (int ni = 0; ni < 4; ni++) {
            int col = noff + ni * 8 + tg * 2;
            float2 b2 = ((const float2*)bias)[col >> 1];
#pragma unroll
            for (int mi = 0; mi < 4; mi++) {
                int t = (mi * 4 + ni) * 4;
                float2 p01 = *(const float2*)(red + slot + t);
                float2 p23 = *(const float2*)(red + slot + t + 2);
                int row0 = tile * TILE + moff + mi * 16 + g;
                int row1 = row0 + 8;
                if (row0 < N_NODES) {
                    float2 o;
                    o.x = fmaxf(acc[mi][ni][0] + p01.x + b2.x, 0.f);
                    o.y = fmaxf(acc[mi][ni][1] + p01.y + b2.y, 0.f);
                    ((float2*)out)[row0 * 64 + (col >> 1)] = o;
                }
                if (row1 < N_NODES) {
                    float2 o;
                    o.x = fmaxf(acc[mi][ni][2] + p23.x + b2.x, 0.f);
                    o.y = fmaxf(acc[mi][ni][3] + p23.y + b2.y, 0.f);
                    ((float2*)out)[row1 * 64 + (col >> 1)] = o;
                }
            }
        }
    }
}

// ---------------- launcher ----------------
extern "C" void kernel_launch(void* const* d_in, const int* in_sizes, int n_in,
                              void* d_out, int out_size) {
    const float* x    = (const float*)d_in[0];
    const int*   ei   = (const int*)d_in[1];
    const int*   et   = (const int*)d_in[2];
    const float* W    = (const float*)d_in[3];
    const float* root = (const float*)d_in[4];
    const float* bias = (const float*)d_in[5];
    float* out = (float*)d_out;

    cudaFuncSetAttribute(k_main, cudaFuncAttributeMaxDynamicSharedMemorySize, SMEM_TOTAL);

    // zero histogram + weight prep fused: 782 blocks zero, 145 blocks prep
    k_zero_prep<<<782 + 145, 1024>>>(W, root);
    k_hist<<<(N_EDGES + 255) / 256, 256>>>(ei, et);
    k_scan_block<<<SCAN_NB, 1024>>>();
    k_scan_sums<<<1, 256>>>();
    k_scan_add<<<SCAN_NB, 1024>>>();
    k_scatter<<<(N_EDGES + 255) / 256, 256>>>(ei, et);
    k_main<<<N_TILES, 512, SMEM_TOTAL>>>(x, bias, out);
}